// round 17
// baseline (speedup 1.0000x reference)
#include <cuda_runtime.h>
#include <cuda_fp16.h>
#include <cstdint>
#include <cstring>
#include <algorithm>

// ===================== Problem constants (static graph) =====================
#define VOCAB    512
#define T_LEN    64
#define D_MODEL  32
#define N_NODES  4000
#define N_LAYERS 5
#define N_BIAS   2
#define BATCH    512
#define N_IN     (T_LEN * D_MODEL)          // 2048
#define N_SRC0   (N_IN + N_BIAS)            // 2050 : first dst node id
#define N_DST    (N_NODES - N_SRC0)         // 1950 : hidden + vocab dst nodes
#define MAX_EDGES  262144                   // raw edges ~166.8k
#define MAX_PADDED 294912                   // per-row 32-padded records + guard

// ===================== Device globals (no allocation allowed) ===============
__device__ float2 g_packed[MAX_PADDED];                   // {weight, __int_as_float(src*BATCH)}
__device__ int2   g_jobtab[N_DST + 1];                    // per dst row: {rec offset, nchunks}
__device__ __align__(128) __half g_vals[N_NODES * BATCH]; // fp16 activation slab (4.1 MB)

// ===================== Host-side: numpy-exact MT19937 =======================
struct MT19937 {
    uint32_t mt[624];
    int idx;
    void seed(uint32_t s) {
        mt[0] = s;
        for (int i = 1; i < 624; i++)
            mt[i] = 1812433253u * (mt[i - 1] ^ (mt[i - 1] >> 30)) + (uint32_t)i;
        idx = 624;
    }
    inline uint32_t next() {
        if (idx >= 624) {
            for (int i = 0; i < 624; i++) {
                uint32_t y = (mt[i] & 0x80000000u) | (mt[(i + 1) % 624] & 0x7fffffffu);
                mt[i] = mt[(i + 397) % 624] ^ (y >> 1);
                if (y & 1u) mt[i] ^= 0x9908b0dfu;
            }
            idx = 0;
        }
        uint32_t y = mt[idx++];
        y ^= y >> 11;
        y ^= (y << 7)  & 0x9d2c5680u;
        y ^= (y << 15) & 0xefc60000u;
        y ^= y >> 18;
        return y;
    }
    inline double rdouble() {  // numpy legacy rk_double
        uint32_t a = next() >> 5, b = next() >> 6;
        return ((double)a * 67108864.0 + (double)b) / 9007199254740992.0;
    }
    inline uint64_t next64() {  // numpy mt19937_next64: hi then lo
        uint64_t hi = next();
        uint64_t lo = next();
        return (hi << 32) | lo;
    }
};

// ===================== Host graph build (exact numpy replica) ===============
struct LayerInfo { int node_base; int row_base; int size; };

static uint32_t  h_pmeta[MAX_PADDED];  // (widx<<12)|src, 0xFFFFFFFF = pad
static int2      h_jobtab[N_DST + 1];  // {offset, nchunks} per dst row
static LayerInfo h_layers[N_LAYERS + 1];
static int       h_npad;

static void build_graph_host() {
    MT19937 mt;
    mt.seed(0u);

    int sizes[N_LAYERS + 1];
    {
        int nh = N_NODES - N_SRC0 - VOCAB;  // 1438
        for (int i = 0; i < N_LAYERS; i++)
            sizes[i] = nh / N_LAYERS + (i < nh % N_LAYERS ? 1 : 0);
        sizes[N_LAYERS] = VOCAB;
    }

    static int esrc[MAX_EDGES];
    static int edst[MAX_EDGES];

    int start = N_SRC0;
    int row_base = 0;
    int rec_off = 0;
    int eidx = 0;

    for (int l = 0; l < N_LAYERS + 1; l++) {
        int size = sizes[l];
        int lbase = eidx;
        int colcnt[VOCAB];
        for (int v = 0; v < size; v++) colcnt[v] = 0;

        for (int u = 0; u < start; u++) {
            for (int v = 0; v < size; v++) {
                double x = mt.rdouble();
                if (x < 0.03) {
                    esrc[eidx] = u;
                    edst[eidx] = v;
                    colcnt[v]++;
                    eidx++;
                }
            }
        }

        // empty-column fix (probability ~1e-24; exact replica anyway)
        int emptyCols[VOCAB], nEmpty = 0;
        for (int v = 0; v < size; v++) if (colcnt[v] == 0) emptyCols[nEmpty++] = v;
        if (nEmpty) {
            uint64_t rng = (uint64_t)(start - 1);
            uint64_t mask = rng;
            mask |= mask >> 1; mask |= mask >> 2; mask |= mask >> 4;
            mask |= mask >> 8; mask |= mask >> 16; mask |= mask >> 32;
            for (int k = 0; k < nEmpty; k++) {
                uint64_t val;
                do { val = mt.next64() & mask; } while (val > rng);
                esrc[eidx] = (int)val;
                edst[eidx] = emptyCols[k];
                colcnt[emptyCols[k]]++;
                eidx++;
            }
            struct P { int s, d; };
            static P tmp[MAX_EDGES];
            int n = eidx - lbase;
            for (int i = 0; i < n; i++) tmp[i] = {esrc[lbase + i], edst[lbase + i]};
            std::sort(tmp, tmp + n, [](const P& a, const P& b) {
                return a.s != b.s ? a.s < b.s : a.d < b.d;
            });
            for (int i = 0; i < n; i++) { esrc[lbase + i] = tmp[i].s; edst[lbase + i] = tmp[i].d; }
        }

        // per-row layout: each row padded to a multiple of 32 records
        int rowoff[VOCAB];
        for (int v = 0; v < size; v++) {
            int padlen = (std::max(colcnt[v], 1) + 31) & ~31;
            rowoff[v] = rec_off;
            h_jobtab[row_base + v].x = rec_off;
            h_jobtab[row_base + v].y = padlen >> 5;   // nchunks
            memset(h_pmeta + rec_off, 0xFF, (size_t)padlen * sizeof(uint32_t));
            rec_off += padlen;
        }

        // scatter edges; weight index = src-major position (== e)
        int fill[VOCAB];
        for (int v = 0; v < size; v++) fill[v] = 0;
        for (int e = lbase; e < eidx; e++) {
            int v = edst[e];
            h_pmeta[rowoff[v] + fill[v]] = ((uint32_t)e << 12) | (uint32_t)esrc[e];
            fill[v]++;
        }

        h_layers[l].node_base = start;
        h_layers[l].row_base  = row_base;
        h_layers[l].size      = size;
        row_base += size;
        start    += size;
    }
    // guard region for last-chunk prefetch overrun
    memset(h_pmeta + rec_off, 0xFF, 32 * sizeof(uint32_t));
    h_npad = rec_off + 32;
}

// ===================== Kernels ==============================================

// Pull padded graph meta + job table from HOST memory (Grace ATS), gather
// runtime weights, write packed records {w, src_offset}; pads become {0,0}.
__global__ void pull_pack_kernel(const uint32_t* __restrict__ hostE,
                                 const int2*     __restrict__ hostJ,
                                 const float*    __restrict__ weights,
                                 int nP) {
    int i = blockIdx.x * blockDim.x + threadIdx.x;
    int stride = gridDim.x * blockDim.x;
    for (int e = i; e < nP; e += stride) {
        uint32_t v = hostE[e];
        float2 rec;
        if (v == 0xFFFFFFFFu) {
            rec = make_float2(0.0f, __int_as_float(0));
        } else {
            rec = make_float2(weights[v >> 12], __int_as_float((int)(v & 0xFFFu) * BATCH));
        }
        g_packed[e] = rec;
    }
    for (int r = i; r < N_DST; r += stride)
        g_jobtab[r] = hostJ[r];
}

// vals[node][b] for input + bias nodes (fp16)
__global__ void embed_kernel(const int* __restrict__ ids,
                             const float* __restrict__ tok,
                             const float* __restrict__ pos) {
    int b    = blockIdx.x * 32 + (threadIdx.x & 31);
    int node = blockIdx.y * 8 + (threadIdx.x >> 5);
    if (node >= N_SRC0) return;
    float v;
    if (node < N_IN) {
        int t = node >> 5;          // node = t*D + d, D = 32
        v = tok[ids[b * T_LEN + t] * D_MODEL + (node & 31)] + pos[node];
    } else {
        v = 1.0f;
    }
    g_vals[node * BATCH + b] = __float2half_rn(v);
}

// ONE WARP = one (dst row, 128-col group), end-to-end. No block barriers,
// no cross-warp reduce. Records staged warp-privately: one coalesced
// LDG.64/lane fetches 32 records; inner loop reads them via LDS (fixed
// latency), so the 32 value LDG.64s pipeline with deep MLP. Double-buffered
// chunks with __syncwarp only. Rows padded per-row to multiples of 32.
__global__ void __launch_bounds__(256, 8)
layer_kernel(float* __restrict__ out,
             int node_base, int row_base, int size, int is_last) {
    __shared__ float2 srec[8][2][32];

    int wid  = threadIdx.x >> 5;
    int lane = threadIdx.x & 31;
    int gw   = blockIdx.x * 8 + wid;
    if (gw >= size * 4) return;
    int dst = gw >> 2;
    int c   = (gw & 3) * 128 + lane * 4;    // 4 consecutive batch columns

    const int2 job = g_jobtab[row_base + dst];    // {offset, nchunks}
    const float2* rec = g_packed + job.x;
    const int nch = job.y;

    float4 A = make_float4(0.f, 0.f, 0.f, 0.f);

    // stage chunk 0
    srec[wid][0][lane] = rec[lane];
    __syncwarp();

    for (int ch = 0; ch < nch; ch++) {
        int bk = ch & 1;
        float2 nxt = rec[(ch + 1) * 32 + lane];   // prefetch (guard-padded)
        #pragma unroll
        for (int i = 0; i < 32; i++) {
            float2 p = srec[wid][bk][i];          // LDS broadcast: fixed latency
            uint2 rv = *(const uint2*)(g_vals + (__float_as_int(p.y) + c));
            float2 f0 = __half22float2(*reinterpret_cast<__half2*>(&rv.x));
            float2 f1 = __half22float2(*reinterpret_cast<__half2*>(&rv.y));
            A.x = fmaf(p.x, f0.x, A.x);
            A.y = fmaf(p.x, f0.y, A.y);
            A.z = fmaf(p.x, f1.x, A.z);
            A.w = fmaf(p.x, f1.y, A.w);
        }
        srec[wid][bk ^ 1][lane] = nxt;
        __syncwarp();
    }

    if (is_last) {
        out[(c    ) * VOCAB + dst] = A.x;   // logits [B, V] row-major, fp32
        out[(c + 1) * VOCAB + dst] = A.y;
        out[(c + 2) * VOCAB + dst] = A.z;
        out[(c + 3) * VOCAB + dst] = A.w;
    } else {
        __half2 h0 = __floats2half2_rn(tanhf(A.x), tanhf(A.y));
        __half2 h1 = __floats2half2_rn(tanhf(A.z), tanhf(A.w));
        uint2 raw;
        raw.x = *reinterpret_cast<uint32_t*>(&h0);
        raw.y = *reinterpret_cast<uint32_t*>(&h1);
        *(uint2*)(g_vals + ((node_base + dst) * BATCH + c)) = raw;
    }
}

// ===================== Launch ===============================================
extern "C" void kernel_launch(void* const* d_in, const int* in_sizes, int n_in,
                              void* d_out, int out_size) {
    const int*   ids = (const int*)  d_in[0];
    const float* tok = (const float*)d_in[1];
    const float* pos = (const float*)d_in[2];
    const float* wts = (const float*)d_in[3];
    float*       out = (float*)d_out;

    // Host-side, deterministic, rebuilt identically on every call.
    build_graph_host();

    pull_pack_kernel<<<512, 256>>>(h_pmeta, h_jobtab, wts, h_npad);

    embed_kernel<<<dim3(BATCH / 32, (N_SRC0 + 7) / 8), 256>>>(ids, tok, pos);

    for (int l = 0; l < N_LAYERS + 1; l++) {
        int sz     = h_layers[l].size;
        int jobs   = sz * 4;
        int blocks = (jobs + 7) / 8;
        layer_kernel<<<blocks, 256>>>(
            out, h_layers[l].node_base, h_layers[l].row_base, sz,
            l == N_LAYERS ? 1 : 0);
    }
}